// round 7
// baseline (speedup 1.0000x reference)
#include <cuda_runtime.h>
#include <cstdint>

// Voxels_40518721470753 — persistent software-pipelined version.
// out[0:3N] = sigmoid(rgb) ([N,3]); out[3N:4N] = relu(dens*10)
// idx(v) = ((int)floorf(v*128+64) - 1) & 127 ; !cond -> rgb 0.5, dens 0
//
// Each block loops over tiles (1024 pts) with double-buffered TMA X loads;
// TMA bulk stores for outputs; gathers stay branchless predicated LDG.128.
// No CUDA API calls in kernel_launch (graph-capture safe).

#define NB        128
#define TPB       256
#define PPB       1024
#define XB_BYTES  (PPB * 3 * 4)   // 12288
#define D_BYTES   (PPB * 4)       // 4096
#define NUM_SMS   148
#define BLK_PER_SM 5

__device__ __forceinline__ uint32_t smem_u32(const void* p) {
    return (uint32_t)__cvta_generic_to_shared(p);
}
__device__ __forceinline__ float fast_sigmoid(float v) {
    return 1.0f / (1.0f + __expf(-v));
}
__device__ __forceinline__ int to_idx(float v) {
    return (((int)floorf(v * 128.0f + 64.0f)) - 1) & (NB - 1);
}
__device__ __forceinline__ void mbar_wait(uint32_t mb, int parity) {
    asm volatile(
        "{\n\t"
        ".reg .pred P;\n\t"
        "W%=:\n\t"
        "mbarrier.try_wait.parity.shared::cta.b64 P, [%0], %1, 10000000;\n\t"
        "@!P bra W%=;\n\t"
        "}"
        :: "r"(mb), "r"(parity) : "memory");
}
__device__ __forceinline__ void tma_load_x(uint32_t dst, const float* src,
                                           uint32_t mb) {
    asm volatile("mbarrier.arrive.expect_tx.shared::cta.b64 _, [%0], %1;"
                 :: "r"(mb), "n"(XB_BYTES) : "memory");
    asm volatile(
        "cp.async.bulk.shared::cluster.global.mbarrier::complete_tx::bytes "
        "[%0], [%1], %2, [%3];"
        :: "r"(dst), "l"(src), "n"(XB_BYTES), "r"(mb) : "memory");
}

__global__ __launch_bounds__(TPB) void voxels_kernel(
    const float*  __restrict__ Xg,        // [N,3]
    const float4* __restrict__ vox,       // [128^3] float4
    float*        __restrict__ rgb_out,   // 3N floats
    float*        __restrict__ dens_out,  // N floats
    int ntiles)
{
    __shared__ __align__(128) float4 sX[2][PPB * 3 / 4];  // 2 x 12 KB
    __shared__ __align__(128) float4 sO[PPB * 3 / 4];     // 12 KB rgb
    __shared__ __align__(128) float4 sD[PPB / 4];         // 4 KB dens
    __shared__ __align__(8)   uint64_t mbar[2];

    const int tid    = threadIdx.x;
    const int stride = gridDim.x;

    if (tid < 2) {
        asm volatile("mbarrier.init.shared::cta.b64 [%0], 1;"
                     :: "r"(smem_u32(&mbar[tid])) : "memory");
    }
    __syncthreads();

    const uint32_t mb[2]  = { smem_u32(&mbar[0]), smem_u32(&mbar[1]) };
    const uint32_t sxa[2] = { smem_u32(&sX[0][0]), smem_u32(&sX[1][0]) };

    int ph[2] = {0, 0};

    // prologue: load first tile into buffer 0
    int tile0 = blockIdx.x;
    if (tid == 0 && tile0 < ntiles)
        tma_load_x(sxa[0], Xg + (size_t)tile0 * (PPB * 3), mb[0]);

    int it = 0;
    for (int tile = tile0; tile < ntiles; tile += stride, it++) {
        const int cur = it & 1;
        const int nxt = cur ^ 1;

        // prefetch next tile into the other buffer (ordered behind the
        // previous iteration's __syncthreads -> no readers left)
        const int ntile = tile + stride;
        if (tid == 0 && ntile < ntiles)
            tma_load_x(sxa[nxt], Xg + (size_t)ntile * (PPB * 3), mb[nxt]);

        // wait current X tile
        mbar_wait(mb[cur], ph[cur]);
        ph[cur] ^= 1;

        // ---- compute points 4*tid .. 4*tid+3 of this tile ----
        float4 a = sX[cur][3 * tid + 0];
        float4 b = sX[cur][3 * tid + 1];
        float4 c = sX[cur][3 * tid + 2];

        float px[4] = {a.x, a.w, b.z, c.y};
        float py[4] = {a.y, b.x, b.w, c.z};
        float pz[4] = {a.z, b.y, c.x, c.w};

        int  idx[4];
        bool cd[4];
#pragma unroll
        for (int k = 0; k < 4; k++) {
            float x = px[k], y = py[k], z = pz[k];
            cd[k]  = (fabsf(x) < 0.5f) & (fabsf(y) < 0.5f) & (fabsf(z) < 0.5f);
            idx[k] = (to_idx(x) * NB + to_idx(y)) * NB + to_idx(z);
        }

        float4 v[4];
#pragma unroll
        for (int k = 0; k < 4; k++) {
            float4 g = make_float4(0.f, 0.f, 0.f, 0.f);
            if (cd[k]) g = __ldg(&vox[idx[k]]);   // predicated LDG.E.128
            v[k] = g;
        }

        float ro[12], dv[4];
#pragma unroll
        for (int k = 0; k < 4; k++) {
            ro[3 * k + 0] = fast_sigmoid(v[k].x);
            ro[3 * k + 1] = fast_sigmoid(v[k].y);
            ro[3 * k + 2] = fast_sigmoid(v[k].z);
            dv[k] = fmaxf(v[k].w * 10.0f, 0.0f);
        }

        // ---- drain previous tile's output store before overwriting sO ----
        if (tid == 0)
            asm volatile("cp.async.bulk.wait_group.read 0;" ::: "memory");
        __syncthreads();   // (also: all compute reads of sX[cur] done)

        sO[3 * tid + 0] = make_float4(ro[0], ro[1], ro[2],  ro[3]);
        sO[3 * tid + 1] = make_float4(ro[4], ro[5], ro[6],  ro[7]);
        sO[3 * tid + 2] = make_float4(ro[8], ro[9], ro[10], ro[11]);
        sD[tid]         = make_float4(dv[0], dv[1], dv[2],  dv[3]);
        __syncthreads();

        // ---- issue output stores (overlap with next iteration) ----
        if (tid == 0) {
            asm volatile("fence.proxy.async.shared::cta;" ::: "memory");
            asm volatile(
                "cp.async.bulk.global.shared::cta.bulk_group [%0], [%1], %2;"
                :: "l"(rgb_out + (size_t)tile * (PPB * 3)),
                   "r"(smem_u32(sO)), "n"(XB_BYTES) : "memory");
            asm volatile(
                "cp.async.bulk.global.shared::cta.bulk_group [%0], [%1], %2;"
                :: "l"(dens_out + (size_t)tile * PPB),
                   "r"(smem_u32(sD)), "n"(D_BYTES) : "memory");
            asm volatile("cp.async.bulk.commit_group;" ::: "memory");
        }
    }
    // outstanding bulk stores complete at kernel-completion boundary.
}

extern "C" void kernel_launch(void* const* d_in, const int* in_sizes, int n_in,
                              void* d_out, int out_size)
{
    const float* X      = (const float*)d_in[0];   // [N,3]
    const float* voxels = (const float*)d_in[1];   // [128,128,128,4]

    int n      = in_sizes[0] / 3;                  // 8388608
    int ntiles = n / PPB;                          // 8192

    float* out      = (float*)d_out;
    float* rgb_out  = out;                         // first 3N floats
    float* dens_out = out + 3LL * n;               // last  N floats

    int grid = NUM_SMS * BLK_PER_SM;               // 740 persistent CTAs
    if (grid > ntiles) grid = ntiles;

    voxels_kernel<<<grid, TPB>>>(
        X, (const float4*)voxels, rgb_out, dens_out, ntiles);
}

// round 8
// speedup vs baseline: 1.7379x; 1.7379x over previous
#include <cuda_runtime.h>
#include <cstdint>

// Voxels_40518721470753 — R4 architecture (one tile per block, TMA in/out,
// branchless gathers), scaled to 2048-point tiles / 512 threads.
// out[0:3N] = sigmoid(rgb) ([N,3]); out[3N:4N] = relu(dens*10)
// idx(v) = ((int)floorf(v*128+64) - 1) & 127 ; !cond -> rgb 0.5, dens 0

#define NB        128
#define TPB       512
#define PPB       2048                 // points per block
#define X_BYTES   (PPB * 3 * 4)        // 24576
#define D_BYTES   (PPB * 4)            // 8192

__device__ __forceinline__ uint32_t smem_u32(const void* p) {
    return (uint32_t)__cvta_generic_to_shared(p);
}
__device__ __forceinline__ float fast_sigmoid(float v) {
    return 1.0f / (1.0f + __expf(-v));
}
__device__ __forceinline__ int to_idx(float v) {
    return (((int)floorf(v * 128.0f + 64.0f)) - 1) & (NB - 1);
}

__global__ __launch_bounds__(TPB) void voxels_kernel(
    const float*  __restrict__ Xg,        // [N,3]
    const float4* __restrict__ vox,       // [128^3] float4
    float*        __restrict__ rgb_out,   // 3N floats
    float*        __restrict__ dens_out)  // N floats
{
    __shared__ __align__(128) float4 s_buf[PPB * 3 / 4];  // 24 KB: X, then rgb
    __shared__ __align__(128) float4 s_dens[PPB / 4];     // 8 KB
    __shared__ __align__(8)   uint64_t mbar;

    const int tid = threadIdx.x;
    const long long base = (long long)blockIdx.x * PPB;

    const uint32_t mb = smem_u32(&mbar);
    if (tid == 0) {
        asm volatile("mbarrier.init.shared::cta.b64 [%0], 1;" :: "r"(mb) : "memory");
    }
    __syncthreads();

    // ---- TMA bulk load of this block's X tile ----
    if (tid == 0) {
        asm volatile("mbarrier.arrive.expect_tx.shared::cta.b64 _, [%0], %1;"
                     :: "r"(mb), "n"(X_BYTES) : "memory");
        asm volatile(
            "cp.async.bulk.shared::cluster.global.mbarrier::complete_tx::bytes "
            "[%0], [%1], %2, [%3];"
            :: "r"(smem_u32(s_buf)), "l"(Xg + base * 3), "n"(X_BYTES), "r"(mb)
            : "memory");
    }
    asm volatile(
        "{\n\t"
        ".reg .pred P;\n\t"
        "W%=:\n\t"
        "mbarrier.try_wait.parity.shared::cta.b64 P, [%0], 0, 10000000;\n\t"
        "@!P bra W%=;\n\t"
        "}"
        :: "r"(mb) : "memory");

    // ---- per-thread compute: points 4*tid .. 4*tid+3 ----
    // 48 B lane stride -> conflict-free LDS.128 within quarter-warp phases.
    float4 a = s_buf[3 * tid + 0];
    float4 b = s_buf[3 * tid + 1];
    float4 c = s_buf[3 * tid + 2];

    float px[4] = {a.x, a.w, b.z, c.y};
    float py[4] = {a.y, b.x, b.w, c.z};
    float pz[4] = {a.z, b.y, c.x, c.w};

    int  idx[4];
    bool cd[4];
#pragma unroll
    for (int k = 0; k < 4; k++) {
        float x = px[k], y = py[k], z = pz[k];
        cd[k]  = (fabsf(x) < 0.5f) & (fabsf(y) < 0.5f) & (fabsf(z) < 0.5f);
        idx[k] = (to_idx(x) * NB + to_idx(y)) * NB + to_idx(z);
    }

    // branchless predicated gathers, 4 in flight
    float4 v[4];
#pragma unroll
    for (int k = 0; k < 4; k++) {
        float4 g = make_float4(0.f, 0.f, 0.f, 0.f);
        if (cd[k]) g = __ldg(&vox[idx[k]]);   // predicated LDG.E.128
        v[k] = g;
    }

    float ro[12], dv[4];
#pragma unroll
    for (int k = 0; k < 4; k++) {
        ro[3 * k + 0] = fast_sigmoid(v[k].x);
        ro[3 * k + 1] = fast_sigmoid(v[k].y);
        ro[3 * k + 2] = fast_sigmoid(v[k].z);
        dv[k] = fmaxf(v[k].w * 10.0f, 0.0f);
    }

    // write results back into own smem slots (no cross-thread hazard)
    s_buf[3 * tid + 0] = make_float4(ro[0], ro[1], ro[2],  ro[3]);
    s_buf[3 * tid + 1] = make_float4(ro[4], ro[5], ro[6],  ro[7]);
    s_buf[3 * tid + 2] = make_float4(ro[8], ro[9], ro[10], ro[11]);
    s_dens[tid]        = make_float4(dv[0], dv[1], dv[2],  dv[3]);
    __syncthreads();

    // ---- TMA bulk stores (rgb 24 KB, dens 8 KB) ----
    if (tid == 0) {
        asm volatile("fence.proxy.async.shared::cta;" ::: "memory");
        asm volatile(
            "cp.async.bulk.global.shared::cta.bulk_group [%0], [%1], %2;"
            :: "l"(rgb_out + base * 3), "r"(smem_u32(s_buf)), "n"(X_BYTES)
            : "memory");
        asm volatile(
            "cp.async.bulk.global.shared::cta.bulk_group [%0], [%1], %2;"
            :: "l"(dens_out + base), "r"(smem_u32(s_dens)), "n"(D_BYTES)
            : "memory");
        asm volatile("cp.async.bulk.commit_group;" ::: "memory");
        asm volatile("cp.async.bulk.wait_group.read 0;" ::: "memory");
    }
}

extern "C" void kernel_launch(void* const* d_in, const int* in_sizes, int n_in,
                              void* d_out, int out_size)
{
    const float* X      = (const float*)d_in[0];   // [N,3]
    const float* voxels = (const float*)d_in[1];   // [128,128,128,4]

    int n = in_sizes[0] / 3;                       // 8388608
    int nblocks = n / PPB;                         // 4096

    float* out      = (float*)d_out;
    float* rgb_out  = out;                         // first 3N floats
    float* dens_out = out + 3LL * n;               // last  N floats

    voxels_kernel<<<nblocks, TPB>>>(
        X, (const float4*)voxels, rgb_out, dens_out);
}